// round 1
// baseline (speedup 1.0000x reference)
#include <cuda_runtime.h>

#define HH 96
#define WW 96
#define CC 512
#define DD 64
#define N_POS 73728   // 8*96*96

// ---------------- scratch (device globals: no allocations allowed) ----------
__device__ float g_q[N_POS * DD];
__device__ float g_k[N_POS * DD];
__device__ float g_v[N_POS * CC];
__device__ float g_accv[N_POS * CC];
__device__ float g_mv[N_POS];
__device__ float g_lv[N_POS];

// ---------------- Kernel 1: fused QKV projection GEMM -----------------------
// Grid: (10, 576). Col-tile 0 -> q, 1 -> k, 2..9 -> v cols (ct-2)*64.
// 128x64x16 tiles, 256 threads, 8x4 per-thread microtile, fp32.
__global__ __launch_bounds__(256) void qkv_gemm(
    const float* __restrict__ x,
    const float* __restrict__ Wq, const float* __restrict__ bq,
    const float* __restrict__ Wk, const float* __restrict__ bk,
    const float* __restrict__ Wv, const float* __restrict__ bv)
{
    __shared__ float As[16][132];   // transposed A tile, padded
    __shared__ float Bs[16][68];    // B tile, padded

    const int ct = blockIdx.x;
    const int rowBase = blockIdx.y * 128;

    const float* W; const float* bias; float* dst; int ldw, coff;
    if (ct == 0)      { W = Wq; bias = bq; dst = g_q; ldw = 64;  coff = 0; }
    else if (ct == 1) { W = Wk; bias = bk; dst = g_k; ldw = 64;  coff = 0; }
    else              { W = Wv; bias = bv; dst = g_v; ldw = CC;  coff = (ct - 2) * 64; }

    const int tid = threadIdx.x;
    const int ar = tid >> 2, ac = (tid & 3) << 2;    // A loader: 64 rows x 16 cols (x2 rows)
    const int br = tid >> 4, bc = (tid & 15) << 2;   // B loader: 16 rows x 64 cols
    const int tx = tid & 15, ty = tid >> 4;

    float acc[8][4] = {};

    for (int k0 = 0; k0 < CC; k0 += 16) {
        float4 a0 = *(const float4*)(x + (size_t)(rowBase + ar) * CC + k0 + ac);
        float4 a1 = *(const float4*)(x + (size_t)(rowBase + ar + 64) * CC + k0 + ac);
        float4 b4 = *(const float4*)(W + (size_t)(k0 + br) * ldw + coff + bc);

        As[ac + 0][ar] = a0.x; As[ac + 1][ar] = a0.y;
        As[ac + 2][ar] = a0.z; As[ac + 3][ar] = a0.w;
        As[ac + 0][ar + 64] = a1.x; As[ac + 1][ar + 64] = a1.y;
        As[ac + 2][ar + 64] = a1.z; As[ac + 3][ar + 64] = a1.w;
        *(float4*)&Bs[br][bc] = b4;
        __syncthreads();

        #pragma unroll
        for (int kk = 0; kk < 16; ++kk) {
            float a[8], b[4];
            *(float4*)(a)     = *(const float4*)&As[kk][ty * 8];
            *(float4*)(a + 4) = *(const float4*)&As[kk][ty * 8 + 4];
            *(float4*)(b)     = *(const float4*)&Bs[kk][tx * 4];
            #pragma unroll
            for (int i = 0; i < 8; ++i)
                #pragma unroll
                for (int j = 0; j < 4; ++j)
                    acc[i][j] += a[i] * b[j];
        }
        __syncthreads();
    }

    float4 bia = *(const float4*)(bias + coff + tx * 4);
    #pragma unroll
    for (int i = 0; i < 8; ++i) {
        int r = rowBase + ty * 8 + i;
        float4 o = { acc[i][0] + bia.x, acc[i][1] + bia.y,
                     acc[i][2] + bia.z, acc[i][3] + bia.w };
        *(float4*)(dst + (size_t)r * ldw + coff + tx * 4) = o;
    }
}

// ---------------- shared-memory layout for attention kernels ----------------
// [0 .. 6144)          Qs  (96 x 64)           -- reused as Vs (96 x 128 = 12288 <= 12384)
// [6144 .. 12384)      Ks  (96 x 65, padded)
// [12384 .. 21600)     Ps  (96 x 96)
// [21600 .. 21984)     stats: ms, ls, fv, fh (96 each)
#define SM_KS   6144
#define SM_PS   12384
#define SM_MS   21600
#define SM_LS   21696
#define SM_FV   21792
#define SM_FH   21888
#define SMEM_FLOATS 21984
#define SMEM_BYTES  (SMEM_FLOATS * 4)

// ---------------- Kernel 2: column attention pass (per (b,w)) ---------------
__global__ __launch_bounds__(256, 2) void col_attn()
{
    extern __shared__ float sm[];
    float* Qs = sm;
    float* Ks = sm + SM_KS;
    float* Ps = sm + SM_PS;
    float* Vs = sm;           // overlays Qs+Ks after scores done

    const int tid = threadIdx.x;
    const int b = blockIdx.x / WW;
    const int w = blockIdx.x % WW;

    // load Q,K column slices: q[b, h, w, :], k[b, h, w, :]
    for (int idx = tid; idx < HH * DD; idx += 256) {
        int hh = idx >> 6, c = idx & 63;
        int n = (b * HH + hh) * WW + w;
        Qs[idx] = g_q[(size_t)n * DD + c];
        Ks[hh * 65 + c] = g_k[(size_t)n * DD + c];
    }
    __syncthreads();

    // scores S[h,g] = q_h . k_g, mask diagonal
    for (int e = tid; e < HH * 24; e += 256) {
        int h = e / 24, g = e % 24;
        float s0 = 0.f, s1 = 0.f, s2 = 0.f, s3 = 0.f;
        const float* qr = Qs + h * 64;
        #pragma unroll
        for (int i = 0; i < 64; ++i) {
            float q = qr[i];
            s0 += q * Ks[(g      ) * 65 + i];
            s1 += q * Ks[(g + 24 ) * 65 + i];
            s2 += q * Ks[(g + 48 ) * 65 + i];
            s3 += q * Ks[(g + 72 ) * 65 + i];
        }
        Ps[h * 96 + g     ] = (h == g     ) ? -1e30f : s0;
        Ps[h * 96 + g + 24] = (h == g + 24) ? -1e30f : s1;
        Ps[h * 96 + g + 48] = (h == g + 48) ? -1e30f : s2;
        Ps[h * 96 + g + 72] = (h == g + 72) ? -1e30f : s3;
    }
    __syncthreads();

    // per-row max / sum-exp; normalize P in place; write stats to global
    const int warp = tid >> 5, lane = tid & 31;
    for (int h = warp; h < HH; h += 8) {
        float m = -3.4e38f;
        for (int g = lane; g < HH; g += 32) m = fmaxf(m, Ps[h * 96 + g]);
        #pragma unroll
        for (int o = 16; o; o >>= 1) m = fmaxf(m, __shfl_xor_sync(0xffffffffu, m, o));
        float l = 0.f;
        for (int g = lane; g < HH; g += 32) {
            float p = __expf(Ps[h * 96 + g] - m);
            Ps[h * 96 + g] = p;
            l += p;
        }
        #pragma unroll
        for (int o = 16; o; o >>= 1) l += __shfl_xor_sync(0xffffffffu, l, o);
        if (lane == 0) {
            int n = (b * HH + h) * WW + w;
            g_mv[n] = m;
            g_lv[n] = l;
        }
    }

    // acc_v = P @ V_col, 128-col chunks, 12 rows x 4 cols per thread
    const int tx = tid & 31;   // -> 4 output cols (float4)
    const int wy = tid >> 5;   // -> 12 output rows
    for (int c0 = 0; c0 < CC; c0 += 128) {
        __syncthreads();
        for (int idx = tid; idx < HH * 32; idx += 256) {
            int gg = idx >> 5, c4 = idx & 31;
            ((float4*)Vs)[idx] =
                *(const float4*)(g_v + (size_t)((b * HH + gg) * WW + w) * CC + c0 + c4 * 4);
        }
        __syncthreads();

        float acc[12][4] = {};
        for (int g = 0; g < HH; ++g) {
            float4 v4 = ((const float4*)Vs)[g * 32 + tx];
            #pragma unroll
            for (int i = 0; i < 12; ++i) {
                float p = Ps[(wy * 12 + i) * 96 + g];
                acc[i][0] += p * v4.x; acc[i][1] += p * v4.y;
                acc[i][2] += p * v4.z; acc[i][3] += p * v4.w;
            }
        }
        #pragma unroll
        for (int i = 0; i < 12; ++i) {
            int hh = wy * 12 + i;
            int n = (b * HH + hh) * WW + w;
            float4 o = { acc[i][0], acc[i][1], acc[i][2], acc[i][3] };
            *(float4*)(g_accv + (size_t)n * CC + c0 + tx * 4) = o;
        }
    }
}

// ---------------- Kernel 3: row attention pass + combine (per (b,h)) --------
__global__ __launch_bounds__(256, 2) void row_attn(
    const float* __restrict__ x, const float* __restrict__ gammap,
    float* __restrict__ out)
{
    extern __shared__ float sm[];
    float* Qs = sm;
    float* Ks = sm + SM_KS;
    float* Ps = sm + SM_PS;
    float* Vs = sm;
    float* ms = sm + SM_MS;
    float* ls = sm + SM_LS;
    float* fv = sm + SM_FV;
    float* fh = sm + SM_FH;

    const int tid = threadIdx.x;
    const int b = blockIdx.x / HH;
    const int h = blockIdx.x % HH;
    const int nbase = (b * HH + h) * WW;

    // load Q,K rows (contiguous)
    for (int idx = tid; idx < WW * DD; idx += 256) {
        int wq = idx >> 6, c = idx & 63;
        Qs[idx] = g_q[(size_t)nbase * DD + idx];
        Ks[wq * 65 + c] = g_k[(size_t)nbase * DD + idx];
    }
    // stash column-pass stats (temporarily in fv/fh)
    if (tid < WW) {
        fv[tid] = g_mv[nbase + tid];
        fh[tid] = g_lv[nbase + tid];
    }
    __syncthreads();

    // scores S[w,u] = q_w . k_u (no mask)
    for (int e = tid; e < WW * 24; e += 256) {
        int wq = e / 24, g = e % 24;
        float s0 = 0.f, s1 = 0.f, s2 = 0.f, s3 = 0.f;
        const float* qr = Qs + wq * 64;
        #pragma unroll
        for (int i = 0; i < 64; ++i) {
            float q = qr[i];
            s0 += q * Ks[(g      ) * 65 + i];
            s1 += q * Ks[(g + 24 ) * 65 + i];
            s2 += q * Ks[(g + 48 ) * 65 + i];
            s3 += q * Ks[(g + 72 ) * 65 + i];
        }
        Ps[wq * 96 + g     ] = s0;
        Ps[wq * 96 + g + 24] = s1;
        Ps[wq * 96 + g + 48] = s2;
        Ps[wq * 96 + g + 72] = s3;
    }
    __syncthreads();

    // stats
    const int warp = tid >> 5, lane = tid & 31;
    for (int wq = warp; wq < WW; wq += 8) {
        float m = -3.4e38f;
        for (int g = lane; g < WW; g += 32) m = fmaxf(m, Ps[wq * 96 + g]);
        #pragma unroll
        for (int o = 16; o; o >>= 1) m = fmaxf(m, __shfl_xor_sync(0xffffffffu, m, o));
        float l = 0.f;
        for (int g = lane; g < WW; g += 32) {
            float p = __expf(Ps[wq * 96 + g] - m);
            Ps[wq * 96 + g] = p;
            l += p;
        }
        #pragma unroll
        for (int o = 16; o; o >>= 1) l += __shfl_xor_sync(0xffffffffu, l, o);
        if (lane == 0) { ms[wq] = m; ls[wq] = l; }
    }
    __syncthreads();

    // exact two-branch softmax combine factors
    if (tid < WW) {
        float mh = ms[tid], lh = ls[tid];
        float mv = fv[tid], lv = fh[tid];
        float M  = fmaxf(mh, mv);
        float ev = __expf(mv - M), eh = __expf(mh - M);
        float inv = 1.f / (ev * lv + eh * lh);
        fv[tid] = ev * inv;
        fh[tid] = eh * inv;
    }

    const float gamma = *gammap;
    const int tx = tid & 31;
    const int wy = tid >> 5;
    for (int c0 = 0; c0 < CC; c0 += 128) {
        __syncthreads();
        for (int idx = tid; idx < WW * 32; idx += 256) {
            int u = idx >> 5, c4 = idx & 31;
            ((float4*)Vs)[idx] =
                *(const float4*)(g_v + (size_t)(nbase + u) * CC + c0 + c4 * 4);
        }
        __syncthreads();

        float acc[12][4] = {};
        for (int g = 0; g < WW; ++g) {
            float4 v4 = ((const float4*)Vs)[g * 32 + tx];
            #pragma unroll
            for (int i = 0; i < 12; ++i) {
                float p = Ps[(wy * 12 + i) * 96 + g];
                acc[i][0] += p * v4.x; acc[i][1] += p * v4.y;
                acc[i][2] += p * v4.z; acc[i][3] += p * v4.w;
            }
        }
        #pragma unroll
        for (int i = 0; i < 12; ++i) {
            int wq = wy * 12 + i;
            int n = nbase + wq;
            size_t off = (size_t)n * CC + c0 + tx * 4;
            float4 av = *(const float4*)(g_accv + off);
            float4 xv = *(const float4*)(x + off);
            float fvw = fv[wq], fhw = fh[wq];
            float4 o;
            o.x = xv.x + gamma * (fvw * av.x + fhw * acc[i][0]);
            o.y = xv.y + gamma * (fvw * av.y + fhw * acc[i][1]);
            o.z = xv.z + gamma * (fvw * av.z + fhw * acc[i][2]);
            o.w = xv.w + gamma * (fvw * av.w + fhw * acc[i][3]);
            *(float4*)(out + off) = o;
        }
    }
}

// ---------------- launch ----------------------------------------------------
extern "C" void kernel_launch(void* const* d_in, const int* in_sizes, int n_in,
                              void* d_out, int out_size)
{
    const float* x  = (const float*)d_in[0];
    const float* Wq = (const float*)d_in[1];
    const float* bq = (const float*)d_in[2];
    const float* Wk = (const float*)d_in[3];
    const float* bk = (const float*)d_in[4];
    const float* Wv = (const float*)d_in[5];
    const float* bv = (const float*)d_in[6];
    const float* gm = (const float*)d_in[7];
    float* out = (float*)d_out;

    cudaFuncSetAttribute(col_attn, cudaFuncAttributeMaxDynamicSharedMemorySize, SMEM_BYTES);
    cudaFuncSetAttribute(row_attn, cudaFuncAttributeMaxDynamicSharedMemorySize, SMEM_BYTES);

    dim3 gA(10, 576);
    qkv_gemm<<<gA, 256>>>(x, Wq, bq, Wk, bk, Wv, bv);
    col_attn<<<768, 256, SMEM_BYTES>>>();
    row_attn<<<768, 256, SMEM_BYTES>>>(x, gm, out);
}

// round 2
// speedup vs baseline: 1.5037x; 1.5037x over previous
#include <cuda_runtime.h>
#include <cstdint>

#define HH 96
#define WW 96
#define CC 512
#define DD 64
#define N_POS 73728   // 8*96*96

// ---------------- scratch (device globals: no allocations allowed) ----------
__device__ float g_q[N_POS * DD];
__device__ float g_k[N_POS * DD];
__device__ float g_v[N_POS * CC];
__device__ float g_accv[N_POS * CC];
__device__ float g_mv[N_POS];
__device__ float g_lv[N_POS];

// ---------------- tf32 mma helpers ------------------------------------------
__device__ __forceinline__ uint32_t f2tf32(float f) {
    uint32_t u;
    asm("cvt.rna.tf32.f32 %0, %1;" : "=r"(u) : "f"(f));
    return u;
}

__device__ __forceinline__ void mma_tf32(float* c, const uint32_t* a, const uint32_t* b) {
    asm volatile(
        "mma.sync.aligned.m16n8k8.row.col.f32.tf32.tf32.f32 "
        "{%0,%1,%2,%3}, {%4,%5,%6,%7}, {%8,%9}, {%0,%1,%2,%3};\n"
        : "+f"(c[0]), "+f"(c[1]), "+f"(c[2]), "+f"(c[3])
        : "r"(a[0]), "r"(a[1]), "r"(a[2]), "r"(a[3]),
          "r"(b[0]), "r"(b[1]));
}

// ---------------- Kernel 1: fused QKV projection GEMM (tf32 tensor) ---------
// Grid: (10, 576). Col-tile 0 -> q, 1 -> k, 2..9 -> v cols (ct-2)*64.
// 128x64 tile per block, K-chunk 32. 8 warps in 4(M) x 2(N); warp tile 32x32
// via 2x4 m16n8k8 tf32 MMAs.
__global__ __launch_bounds__(256) void qkv_gemm(
    const float* __restrict__ x,
    const float* __restrict__ Wq, const float* __restrict__ bq,
    const float* __restrict__ Wk, const float* __restrict__ bk,
    const float* __restrict__ Wv, const float* __restrict__ bv)
{
    __shared__ float As[128][36];
    __shared__ float Bs[32][68];

    const int ct = blockIdx.x;
    const int rowBase = blockIdx.y * 128;

    const float* W; const float* bias; float* dst; int ldw, coff;
    if (ct == 0)      { W = Wq; bias = bq; dst = g_q; ldw = 64;  coff = 0; }
    else if (ct == 1) { W = Wk; bias = bk; dst = g_k; ldw = 64;  coff = 0; }
    else              { W = Wv; bias = bv; dst = g_v; ldw = CC;  coff = (ct - 2) * 64; }

    const int tid  = threadIdx.x;
    const int lane = tid & 31;
    const int warp = tid >> 5;
    const int wm   = warp & 3;   // M sub-tile (32 rows)
    const int wn   = warp >> 2;  // N sub-tile (32 cols)
    const int g8   = lane >> 2;  // 0..7
    const int t4   = lane & 3;   // 0..3

    float acc[2][4][4] = {};

    const int arow = tid >> 3;          // 0..31 (x4 passes of 32 rows)
    const int acol = (tid & 7) * 4;
    const int brow = tid >> 4;          // 0..15 (x2 passes of 16 rows)
    const int bcol = (tid & 15) * 4;

    for (int k0 = 0; k0 < CC; k0 += 32) {
        #pragma unroll
        for (int i = 0; i < 4; ++i) {
            float4 a = *(const float4*)(x + (size_t)(rowBase + arow + i * 32) * CC + k0 + acol);
            *(float4*)&As[arow + i * 32][acol] = a;
        }
        #pragma unroll
        for (int i = 0; i < 2; ++i) {
            float4 b4 = *(const float4*)(W + (size_t)(k0 + brow + i * 16) * ldw + coff + bcol);
            *(float4*)&Bs[brow + i * 16][bcol] = b4;
        }
        __syncthreads();

        #pragma unroll
        for (int kk = 0; kk < 4; ++kk) {
            const int kb = kk * 8;
            uint32_t afrag[2][4], bfrag[4][2];
            #pragma unroll
            for (int mi = 0; mi < 2; ++mi) {
                const int r0 = wm * 32 + mi * 16 + g8;
                afrag[mi][0] = f2tf32(As[r0    ][kb + t4    ]);
                afrag[mi][1] = f2tf32(As[r0 + 8][kb + t4    ]);
                afrag[mi][2] = f2tf32(As[r0    ][kb + t4 + 4]);
                afrag[mi][3] = f2tf32(As[r0 + 8][kb + t4 + 4]);
            }
            #pragma unroll
            for (int ni = 0; ni < 4; ++ni) {
                const int n = wn * 32 + ni * 8 + g8;
                bfrag[ni][0] = f2tf32(Bs[kb + t4    ][n]);
                bfrag[ni][1] = f2tf32(Bs[kb + t4 + 4][n]);
            }
            #pragma unroll
            for (int mi = 0; mi < 2; ++mi)
                #pragma unroll
                for (int ni = 0; ni < 4; ++ni)
                    mma_tf32(acc[mi][ni], afrag[mi], bfrag[ni]);
        }
        __syncthreads();
    }

    // epilogue: add bias, write directly (c frag: rows g8 / g8+8, cols 2*t4, 2*t4+1)
    #pragma unroll
    for (int ni = 0; ni < 4; ++ni) {
        const int col = coff + wn * 32 + ni * 8 + 2 * t4;
        const float b0 = bias[col], b1 = bias[col + 1];
        #pragma unroll
        for (int mi = 0; mi < 2; ++mi) {
            const int r0 = rowBase + wm * 32 + mi * 16 + g8;
            float2 o0 = { acc[mi][ni][0] + b0, acc[mi][ni][1] + b1 };
            float2 o1 = { acc[mi][ni][2] + b0, acc[mi][ni][3] + b1 };
            *(float2*)(dst + (size_t)r0 * ldw + col) = o0;
            *(float2*)(dst + (size_t)(r0 + 8) * ldw + col) = o1;
        }
    }
}

// ---------------- shared-memory layout for attention kernels ----------------
#define SM_KS   6144
#define SM_PS   12384
#define SM_MS   21600
#define SM_LS   21696
#define SM_FV   21792
#define SM_FH   21888
#define SMEM_FLOATS 21984
#define SMEM_BYTES  (SMEM_FLOATS * 4)

// ---------------- Kernel 2: column attention pass (per (b,w)) ---------------
__global__ __launch_bounds__(256, 2) void col_attn()
{
    extern __shared__ float sm[];
    float* Qs = sm;
    float* Ks = sm + SM_KS;
    float* Ps = sm + SM_PS;
    float* Vs = sm;           // overlays Qs+Ks after scores done

    const int tid = threadIdx.x;
    const int b = blockIdx.x / WW;
    const int w = blockIdx.x % WW;

    for (int idx = tid; idx < HH * DD; idx += 256) {
        int hh = idx >> 6, c = idx & 63;
        int n = (b * HH + hh) * WW + w;
        Qs[idx] = g_q[(size_t)n * DD + c];
        Ks[hh * 65 + c] = g_k[(size_t)n * DD + c];
    }
    __syncthreads();

    for (int e = tid; e < HH * 24; e += 256) {
        int h = e / 24, g = e % 24;
        float s0 = 0.f, s1 = 0.f, s2 = 0.f, s3 = 0.f;
        const float* qr = Qs + h * 64;
        #pragma unroll
        for (int i = 0; i < 64; ++i) {
            float q = qr[i];
            s0 += q * Ks[(g      ) * 65 + i];
            s1 += q * Ks[(g + 24 ) * 65 + i];
            s2 += q * Ks[(g + 48 ) * 65 + i];
            s3 += q * Ks[(g + 72 ) * 65 + i];
        }
        Ps[h * 96 + g     ] = (h == g     ) ? -1e30f : s0;
        Ps[h * 96 + g + 24] = (h == g + 24) ? -1e30f : s1;
        Ps[h * 96 + g + 48] = (h == g + 48) ? -1e30f : s2;
        Ps[h * 96 + g + 72] = (h == g + 72) ? -1e30f : s3;
    }
    __syncthreads();

    const int warp = tid >> 5, lane = tid & 31;
    for (int h = warp; h < HH; h += 8) {
        float m = -3.4e38f;
        for (int g = lane; g < HH; g += 32) m = fmaxf(m, Ps[h * 96 + g]);
        #pragma unroll
        for (int o = 16; o; o >>= 1) m = fmaxf(m, __shfl_xor_sync(0xffffffffu, m, o));
        float l = 0.f;
        for (int g = lane; g < HH; g += 32) {
            float p = __expf(Ps[h * 96 + g] - m);
            Ps[h * 96 + g] = p;
            l += p;
        }
        #pragma unroll
        for (int o = 16; o; o >>= 1) l += __shfl_xor_sync(0xffffffffu, l, o);
        if (lane == 0) {
            int n = (b * HH + h) * WW + w;
            g_mv[n] = m;
            g_lv[n] = l;
        }
    }

    const int tx = tid & 31;
    const int wy = tid >> 5;
    for (int c0 = 0; c0 < CC; c0 += 128) {
        __syncthreads();
        for (int idx = tid; idx < HH * 32; idx += 256) {
            int gg = idx >> 5, c4 = idx & 31;
            ((float4*)Vs)[idx] =
                *(const float4*)(g_v + (size_t)((b * HH + gg) * WW + w) * CC + c0 + c4 * 4);
        }
        __syncthreads();

        float acc[12][4] = {};
        for (int g = 0; g < HH; ++g) {
            float4 v4 = ((const float4*)Vs)[g * 32 + tx];
            #pragma unroll
            for (int i = 0; i < 12; ++i) {
                float p = Ps[(wy * 12 + i) * 96 + g];
                acc[i][0] += p * v4.x; acc[i][1] += p * v4.y;
                acc[i][2] += p * v4.z; acc[i][3] += p * v4.w;
            }
        }
        #pragma unroll
        for (int i = 0; i < 12; ++i) {
            int hh = wy * 12 + i;
            int n = (b * HH + hh) * WW + w;
            float4 o = { acc[i][0], acc[i][1], acc[i][2], acc[i][3] };
            *(float4*)(g_accv + (size_t)n * CC + c0 + tx * 4) = o;
        }
    }
}

// ---------------- Kernel 3: row attention pass + combine (per (b,h)) --------
__global__ __launch_bounds__(256, 2) void row_attn(
    const float* __restrict__ x, const float* __restrict__ gammap,
    float* __restrict__ out)
{
    extern __shared__ float sm[];
    float* Qs = sm;
    float* Ks = sm + SM_KS;
    float* Ps = sm + SM_PS;
    float* Vs = sm;
    float* ms = sm + SM_MS;
    float* ls = sm + SM_LS;
    float* fv = sm + SM_FV;
    float* fh = sm + SM_FH;

    const int tid = threadIdx.x;
    const int b = blockIdx.x / HH;
    const int h = blockIdx.x % HH;
    const int nbase = (b * HH + h) * WW;

    for (int idx = tid; idx < WW * DD; idx += 256) {
        int wq = idx >> 6, c = idx & 63;
        Qs[idx] = g_q[(size_t)nbase * DD + idx];
        Ks[wq * 65 + c] = g_k[(size_t)nbase * DD + idx];
    }
    if (tid < WW) {
        fv[tid] = g_mv[nbase + tid];
        fh[tid] = g_lv[nbase + tid];
    }
    __syncthreads();

    for (int e = tid; e < WW * 24; e += 256) {
        int wq = e / 24, g = e % 24;
        float s0 = 0.f, s1 = 0.f, s2 = 0.f, s3 = 0.f;
        const float* qr = Qs + wq * 64;
        #pragma unroll
        for (int i = 0; i < 64; ++i) {
            float q = qr[i];
            s0 += q * Ks[(g      ) * 65 + i];
            s1 += q * Ks[(g + 24 ) * 65 + i];
            s2 += q * Ks[(g + 48 ) * 65 + i];
            s3 += q * Ks[(g + 72 ) * 65 + i];
        }
        Ps[wq * 96 + g     ] = s0;
        Ps[wq * 96 + g + 24] = s1;
        Ps[wq * 96 + g + 48] = s2;
        Ps[wq * 96 + g + 72] = s3;
    }
    __syncthreads();

    const int warp = tid >> 5, lane = tid & 31;
    for (int wq = warp; wq < WW; wq += 8) {
        float m = -3.4e38f;
        for (int g = lane; g < WW; g += 32) m = fmaxf(m, Ps[wq * 96 + g]);
        #pragma unroll
        for (int o = 16; o; o >>= 1) m = fmaxf(m, __shfl_xor_sync(0xffffffffu, m, o));
        float l = 0.f;
        for (int g = lane; g < WW; g += 32) {
            float p = __expf(Ps[wq * 96 + g] - m);
            Ps[wq * 96 + g] = p;
            l += p;
        }
        #pragma unroll
        for (int o = 16; o; o >>= 1) l += __shfl_xor_sync(0xffffffffu, l, o);
        if (lane == 0) { ms[wq] = m; ls[wq] = l; }
    }
    __syncthreads();

    if (tid < WW) {
        float mh = ms[tid], lh = ls[tid];
        float mv = fv[tid], lv = fh[tid];
        float M  = fmaxf(mh, mv);
        float ev = __expf(mv - M), eh = __expf(mh - M);
        float inv = 1.f / (ev * lv + eh * lh);
        fv[tid] = ev * inv;
        fh[tid] = eh * inv;
    }

    const float gamma = *gammap;
    const int tx = tid & 31;
    const int wy = tid >> 5;
    for (int c0 = 0; c0 < CC; c0 += 128) {
        __syncthreads();
        for (int idx = tid; idx < WW * 32; idx += 256) {
            int u = idx >> 5, c4 = idx & 31;
            ((float4*)Vs)[idx] =
                *(const float4*)(g_v + (size_t)(nbase + u) * CC + c0 + c4 * 4);
        }
        __syncthreads();

        float acc[12][4] = {};
        for (int g = 0; g < WW; ++g) {
            float4 v4 = ((const float4*)Vs)[g * 32 + tx];
            #pragma unroll
            for (int i = 0; i < 12; ++i) {
                float p = Ps[(wy * 12 + i) * 96 + g];
                acc[i][0] += p * v4.x; acc[i][1] += p * v4.y;
                acc[i][2] += p * v4.z; acc[i][3] += p * v4.w;
            }
        }
        #pragma unroll
        for (int i = 0; i < 12; ++i) {
            int wq = wy * 12 + i;
            int n = nbase + wq;
            size_t off = (size_t)n * CC + c0 + tx * 4;
            float4 av = *(const float4*)(g_accv + off);
            float4 xv = *(const float4*)(x + off);
            float fvw = fv[wq], fhw = fh[wq];
            float4 o;
            o.x = xv.x + gamma * (fvw * av.x + fhw * acc[i][0]);
            o.y = xv.y + gamma * (fvw * av.y + fhw * acc[i][1]);
            o.z = xv.z + gamma * (fvw * av.z + fhw * acc[i][2]);
            o.w = xv.w + gamma * (fvw * av.w + fhw * acc[i][3]);
            *(float4*)(out + off) = o;
        }
    }
}

// ---------------- launch ----------------------------------------------------
extern "C" void kernel_launch(void* const* d_in, const int* in_sizes, int n_in,
                              void* d_out, int out_size)
{
    const float* x  = (const float*)d_in[0];
    const float* Wq = (const float*)d_in[1];
    const float* bq = (const float*)d_in[2];
    const float* Wk = (const float*)d_in[3];
    const float* bk = (const float*)d_in[4];
    const float* Wv = (const float*)d_in[5];
    const float* bv = (const float*)d_in[6];
    const float* gm = (const float*)d_in[7];
    float* out = (float*)d_out;

    cudaFuncSetAttribute(col_attn, cudaFuncAttributeMaxDynamicSharedMemorySize, SMEM_BYTES);
    cudaFuncSetAttribute(row_attn, cudaFuncAttributeMaxDynamicSharedMemorySize, SMEM_BYTES);

    dim3 gA(10, 576);
    qkv_gemm<<<gA, 256>>>(x, Wq, bq, Wk, bk, Wv, bv);
    col_attn<<<768, 256, SMEM_BYTES>>>();
    row_attn<<<768, 256, SMEM_BYTES>>>(x, gm, out);
}

// round 3
// speedup vs baseline: 1.9019x; 1.2648x over previous
#include <cuda_runtime.h>
#include <cstdint>

#define HH 96
#define WW 96
#define CC 512
#define DD 64
#define N_POS 73728   // 8*96*96

// ---------------- scratch (device globals: no allocations allowed) ----------
__device__ float g_q[N_POS * DD];
__device__ float g_k[N_POS * DD];
__device__ float g_v[N_POS * CC];
__device__ float g_accv[N_POS * CC];
__device__ float g_mv[N_POS];
__device__ float g_lv[N_POS];

// ---------------- tf32 mma helpers ------------------------------------------
__device__ __forceinline__ uint32_t f2tf32(float f) {
    uint32_t u;
    asm("cvt.rna.tf32.f32 %0, %1;" : "=r"(u) : "f"(f));
    return u;
}

__device__ __forceinline__ void mma_tf32(float* c, const uint32_t* a, const uint32_t* b) {
    asm volatile(
        "mma.sync.aligned.m16n8k8.row.col.f32.tf32.tf32.f32 "
        "{%0,%1,%2,%3}, {%4,%5,%6,%7}, {%8,%9}, {%0,%1,%2,%3};\n"
        : "+f"(c[0]), "+f"(c[1]), "+f"(c[2]), "+f"(c[3])
        : "r"(a[0]), "r"(a[1]), "r"(a[2]), "r"(a[3]),
          "r"(b[0]), "r"(b[1]));
}

// ---------------- Kernel 1: fused QKV projection GEMM (tf32 tensor) ---------
// Grid: (10, 576). Col-tile 0 -> q, 1 -> k, 2..9 -> v cols (ct-2)*64.
// 128x64 tile, K-chunk 32, smem holds PRE-CONVERTED tf32; next chunk
// prefetched into registers during the MMA phase.
__global__ __launch_bounds__(256) void qkv_gemm(
    const float* __restrict__ x,
    const float* __restrict__ Wq, const float* __restrict__ bq,
    const float* __restrict__ Wk, const float* __restrict__ bk,
    const float* __restrict__ Wv, const float* __restrict__ bv)
{
    __shared__ uint32_t As[128][36];
    __shared__ uint32_t Bs[32][68];

    const int ct = blockIdx.x;
    const int rowBase = blockIdx.y * 128;

    const float* W; const float* bias; float* dst; int ldw, coff;
    if (ct == 0)      { W = Wq; bias = bq; dst = g_q; ldw = 64;  coff = 0; }
    else if (ct == 1) { W = Wk; bias = bk; dst = g_k; ldw = 64;  coff = 0; }
    else              { W = Wv; bias = bv; dst = g_v; ldw = CC;  coff = (ct - 2) * 64; }

    const int tid  = threadIdx.x;
    const int lane = tid & 31;
    const int warp = tid >> 5;
    const int wm   = warp & 3;   // M sub-tile (32 rows)
    const int wn   = warp >> 2;  // N sub-tile (32 cols)
    const int g8   = lane >> 2;
    const int t4   = lane & 3;

    const int arow = tid >> 3;          // 0..31 (x4 groups of 32 rows)
    const int acol = (tid & 7) * 4;
    const int brow = tid >> 4;          // 0..15 (x2 groups of 16 rows)
    const int bcol = (tid & 15) * 4;

    float acc[2][4][4] = {};
    float4 pA[4]; float4 pB[2];

    #pragma unroll
    for (int i = 0; i < 4; ++i)
        pA[i] = *(const float4*)(x + (size_t)(rowBase + arow + i * 32) * CC + acol);
    #pragma unroll
    for (int i = 0; i < 2; ++i)
        pB[i] = *(const float4*)(W + (size_t)(brow + i * 16) * ldw + coff + bcol);

    for (int k0 = 0; k0 < CC; k0 += 32) {
        #pragma unroll
        for (int i = 0; i < 4; ++i) {
            uint4 u = { f2tf32(pA[i].x), f2tf32(pA[i].y), f2tf32(pA[i].z), f2tf32(pA[i].w) };
            *(uint4*)&As[arow + i * 32][acol] = u;
        }
        #pragma unroll
        for (int i = 0; i < 2; ++i) {
            uint4 u = { f2tf32(pB[i].x), f2tf32(pB[i].y), f2tf32(pB[i].z), f2tf32(pB[i].w) };
            *(uint4*)&Bs[brow + i * 16][bcol] = u;
        }
        __syncthreads();

        if (k0 + 32 < CC) {
            #pragma unroll
            for (int i = 0; i < 4; ++i)
                pA[i] = *(const float4*)(x + (size_t)(rowBase + arow + i * 32) * CC + k0 + 32 + acol);
            #pragma unroll
            for (int i = 0; i < 2; ++i)
                pB[i] = *(const float4*)(W + (size_t)(k0 + 32 + brow + i * 16) * ldw + coff + bcol);
        }

        #pragma unroll
        for (int kk = 0; kk < 4; ++kk) {
            const int kb = kk * 8;
            uint32_t afrag[2][4], bfrag[4][2];
            #pragma unroll
            for (int mi = 0; mi < 2; ++mi) {
                const int r0 = wm * 32 + mi * 16 + g8;
                afrag[mi][0] = As[r0    ][kb + t4    ];
                afrag[mi][1] = As[r0 + 8][kb + t4    ];
                afrag[mi][2] = As[r0    ][kb + t4 + 4];
                afrag[mi][3] = As[r0 + 8][kb + t4 + 4];
            }
            #pragma unroll
            for (int ni = 0; ni < 4; ++ni) {
                const int n = wn * 32 + ni * 8 + g8;
                bfrag[ni][0] = Bs[kb + t4    ][n];
                bfrag[ni][1] = Bs[kb + t4 + 4][n];
            }
            #pragma unroll
            for (int mi = 0; mi < 2; ++mi)
                #pragma unroll
                for (int ni = 0; ni < 4; ++ni)
                    mma_tf32(acc[mi][ni], afrag[mi], bfrag[ni]);
        }
        __syncthreads();
    }

    #pragma unroll
    for (int ni = 0; ni < 4; ++ni) {
        const int col = coff + wn * 32 + ni * 8 + 2 * t4;
        const float b0 = bias[col], b1 = bias[col + 1];
        #pragma unroll
        for (int mi = 0; mi < 2; ++mi) {
            const int r0 = rowBase + wm * 32 + mi * 16 + g8;
            float2 o0 = { acc[mi][ni][0] + b0, acc[mi][ni][1] + b1 };
            float2 o1 = { acc[mi][ni][2] + b0, acc[mi][ni][3] + b1 };
            *(float2*)(dst + (size_t)r0 * ldw + col) = o0;
            *(float2*)(dst + (size_t)(r0 + 8) * ldw + col) = o1;
        }
    }
}

// ---------------- shared-memory layout for attention kernels ----------------
// floats:
// [0 .. 6144)        Qs  (96 x 64)        -- overlaid by Vs (96 x 132 = 12672)
// [6144 .. 12800)    Kt  (64 x 104)       -- (overlay region continues)
// [12800 .. 22400)   Ps  (96 x 100)       fp32 scores -> tf32 bits after softmax
// [22400 .. 22784)   stats: ms, ls, fv, fh
#define KT_STRIDE 104
#define PS_STRIDE 100
#define VS_STRIDE 132
#define SM_KT   6144
#define SM_PS   12800
#define SM_MS   22400
#define SM_LS   22496
#define SM_FV   22592
#define SM_FH   22688
#define SMEM_FLOATS 22784
#define SMEM_BYTES  (SMEM_FLOATS * 4)

// ---------------- Kernel 2: column attention pass (per (b,w)) ---------------
__global__ __launch_bounds__(256, 2) void col_attn()
{
    extern __shared__ float sm[];
    float* Qs = sm;
    float* Kt = sm + SM_KT;
    float* Ps = sm + SM_PS;
    uint32_t* Psu = (uint32_t*)Ps;
    uint32_t* Vsu = (uint32_t*)sm;   // overlays Qs+Kt

    const int tid = threadIdx.x;
    const int b = blockIdx.x / WW;
    const int w = blockIdx.x % WW;

    for (int idx = tid; idx < HH * DD; idx += 256) {
        int hh = idx >> 6, c = idx & 63;
        size_t off = (size_t)((b * HH + hh) * WW + w) * DD + c;
        Qs[idx] = g_q[off];
        Kt[c * KT_STRIDE + hh] = g_k[off];
    }
    __syncthreads();

    // scores S[h,g] (4 consecutive g per thread), mask diagonal
    for (int e = tid; e < HH * 24; e += 256) {
        int h = e / 24, g0 = (e % 24) * 4;
        float4 s = {0.f, 0.f, 0.f, 0.f};
        const float* qr = Qs + h * 64;
        #pragma unroll
        for (int i = 0; i < 64; i += 4) {
            float4 q4 = *(const float4*)(qr + i);
            float4 k0 = *(const float4*)(Kt + (i + 0) * KT_STRIDE + g0);
            float4 k1 = *(const float4*)(Kt + (i + 1) * KT_STRIDE + g0);
            float4 k2 = *(const float4*)(Kt + (i + 2) * KT_STRIDE + g0);
            float4 k3 = *(const float4*)(Kt + (i + 3) * KT_STRIDE + g0);
            s.x += q4.x * k0.x + q4.y * k1.x + q4.z * k2.x + q4.w * k3.x;
            s.y += q4.x * k0.y + q4.y * k1.y + q4.z * k2.y + q4.w * k3.y;
            s.z += q4.x * k0.z + q4.y * k1.z + q4.z * k2.z + q4.w * k3.z;
            s.w += q4.x * k0.w + q4.y * k1.w + q4.z * k2.w + q4.w * k3.w;
        }
        if (h == g0    ) s.x = -1e30f;
        if (h == g0 + 1) s.y = -1e30f;
        if (h == g0 + 2) s.z = -1e30f;
        if (h == g0 + 3) s.w = -1e30f;
        *(float4*)(Ps + h * PS_STRIDE + g0) = s;
    }
    __syncthreads();

    // softmax: stats + in-place convert P to tf32 bits (l from rounded vals)
    const int warp = tid >> 5, lane = tid & 31;
    for (int h = warp; h < HH; h += 8) {
        float m = -3.4e38f;
        for (int g = lane; g < HH; g += 32) m = fmaxf(m, Ps[h * PS_STRIDE + g]);
        #pragma unroll
        for (int o = 16; o; o >>= 1) m = fmaxf(m, __shfl_xor_sync(0xffffffffu, m, o));
        float l = 0.f;
        for (int g = lane; g < HH; g += 32) {
            uint32_t u = f2tf32(__expf(Ps[h * PS_STRIDE + g] - m));
            Psu[h * PS_STRIDE + g] = u;
            l += __uint_as_float(u);
        }
        #pragma unroll
        for (int o = 16; o; o >>= 1) l += __shfl_xor_sync(0xffffffffu, l, o);
        if (lane == 0) {
            int n = (b * HH + h) * WW + w;
            g_mv[n] = m;
            g_lv[n] = l;
        }
    }

    // acc_v = P @ V via tf32 MMA: warps 2(M) x 4(N), warp tile 48x32
    const int g8 = lane >> 2, t4 = lane & 3;
    const int m0 = (warp & 1) * 48, n0 = (warp >> 1) * 32;
    for (int c0 = 0; c0 < CC; c0 += 128) {
        __syncthreads();
        for (int idx = tid; idx < HH * 32; idx += 256) {
            int gg = idx >> 5, c4 = (idx & 31) * 4;
            float4 v = *(const float4*)(g_v + (size_t)((b * HH + gg) * WW + w) * CC + c0 + c4);
            uint4 u = { f2tf32(v.x), f2tf32(v.y), f2tf32(v.z), f2tf32(v.w) };
            *(uint4*)(Vsu + gg * VS_STRIDE + c4) = u;
        }
        __syncthreads();

        float acc[3][4][4] = {};
        #pragma unroll
        for (int ks = 0; ks < 12; ++ks) {
            const int kb = ks * 8;
            uint32_t a[3][4], bf[4][2];
            #pragma unroll
            for (int mi = 0; mi < 3; ++mi) {
                const int r0 = m0 + mi * 16 + g8;
                a[mi][0] = Psu[(r0    ) * PS_STRIDE + kb + t4    ];
                a[mi][1] = Psu[(r0 + 8) * PS_STRIDE + kb + t4    ];
                a[mi][2] = Psu[(r0    ) * PS_STRIDE + kb + t4 + 4];
                a[mi][3] = Psu[(r0 + 8) * PS_STRIDE + kb + t4 + 4];
            }
            #pragma unroll
            for (int ni = 0; ni < 4; ++ni) {
                const int n = n0 + ni * 8 + g8;
                bf[ni][0] = Vsu[(kb + t4    ) * VS_STRIDE + n];
                bf[ni][1] = Vsu[(kb + t4 + 4) * VS_STRIDE + n];
            }
            #pragma unroll
            for (int mi = 0; mi < 3; ++mi)
                #pragma unroll
                for (int ni = 0; ni < 4; ++ni)
                    mma_tf32(acc[mi][ni], a[mi], bf[ni]);
        }

        #pragma unroll
        for (int mi = 0; mi < 3; ++mi) {
            const int rA = m0 + mi * 16 + g8;
            const size_t nA = (size_t)((b * HH + rA    ) * WW + w) * CC;
            const size_t nB = (size_t)((b * HH + rA + 8) * WW + w) * CC;
            #pragma unroll
            for (int ni = 0; ni < 4; ++ni) {
                const int col = c0 + n0 + ni * 8 + 2 * t4;
                float2 o0 = { acc[mi][ni][0], acc[mi][ni][1] };
                float2 o1 = { acc[mi][ni][2], acc[mi][ni][3] };
                *(float2*)(g_accv + nA + col) = o0;
                *(float2*)(g_accv + nB + col) = o1;
            }
        }
    }
}

// ---------------- Kernel 3: row attention pass + combine (per (b,h)) --------
__global__ __launch_bounds__(256, 2) void row_attn(
    const float* __restrict__ x, const float* __restrict__ gammap,
    float* __restrict__ out)
{
    extern __shared__ float sm[];
    float* Qs = sm;
    float* Kt = sm + SM_KT;
    float* Ps = sm + SM_PS;
    uint32_t* Psu = (uint32_t*)Ps;
    uint32_t* Vsu = (uint32_t*)sm;
    float* ms = sm + SM_MS;
    float* ls = sm + SM_LS;
    float* fv = sm + SM_FV;
    float* fh = sm + SM_FH;

    const int tid = threadIdx.x;
    const int b = blockIdx.x / HH;
    const int h = blockIdx.x % HH;
    const int nbase = (b * HH + h) * WW;

    for (int idx = tid; idx < WW * DD; idx += 256) {
        int wq = idx >> 6, c = idx & 63;
        float kval = g_k[(size_t)nbase * DD + idx];
        Qs[idx] = g_q[(size_t)nbase * DD + idx];
        Kt[c * KT_STRIDE + wq] = kval;
    }
    if (tid < WW) {
        fv[tid] = g_mv[nbase + tid];
        fh[tid] = g_lv[nbase + tid];
    }
    __syncthreads();

    for (int e = tid; e < WW * 24; e += 256) {
        int wq = e / 24, g0 = (e % 24) * 4;
        float4 s = {0.f, 0.f, 0.f, 0.f};
        const float* qr = Qs + wq * 64;
        #pragma unroll
        for (int i = 0; i < 64; i += 4) {
            float4 q4 = *(const float4*)(qr + i);
            float4 k0 = *(const float4*)(Kt + (i + 0) * KT_STRIDE + g0);
            float4 k1 = *(const float4*)(Kt + (i + 1) * KT_STRIDE + g0);
            float4 k2 = *(const float4*)(Kt + (i + 2) * KT_STRIDE + g0);
            float4 k3 = *(const float4*)(Kt + (i + 3) * KT_STRIDE + g0);
            s.x += q4.x * k0.x + q4.y * k1.x + q4.z * k2.x + q4.w * k3.x;
            s.y += q4.x * k0.y + q4.y * k1.y + q4.z * k2.y + q4.w * k3.y;
            s.z += q4.x * k0.z + q4.y * k1.z + q4.z * k2.z + q4.w * k3.z;
            s.w += q4.x * k0.w + q4.y * k1.w + q4.z * k2.w + q4.w * k3.w;
        }
        *(float4*)(Ps + wq * PS_STRIDE + g0) = s;
    }
    __syncthreads();

    const int warp = tid >> 5, lane = tid & 31;
    for (int wq = warp; wq < WW; wq += 8) {
        float m = -3.4e38f;
        for (int g = lane; g < WW; g += 32) m = fmaxf(m, Ps[wq * PS_STRIDE + g]);
        #pragma unroll
        for (int o = 16; o; o >>= 1) m = fmaxf(m, __shfl_xor_sync(0xffffffffu, m, o));
        float l = 0.f;
        for (int g = lane; g < WW; g += 32) {
            uint32_t u = f2tf32(__expf(Ps[wq * PS_STRIDE + g] - m));
            Psu[wq * PS_STRIDE + g] = u;
            l += __uint_as_float(u);
        }
        #pragma unroll
        for (int o = 16; o; o >>= 1) l += __shfl_xor_sync(0xffffffffu, l, o);
        if (lane == 0) { ms[wq] = m; ls[wq] = l; }
    }
    __syncthreads();

    if (tid < WW) {
        float mh = ms[tid], lh = ls[tid];
        float mv = fv[tid], lv = fh[tid];
        float M  = fmaxf(mh, mv);
        float ev = __expf(mv - M), eh = __expf(mh - M);
        float inv = 1.f / (ev * lv + eh * lh);
        fv[tid] = ev * inv;
        fh[tid] = eh * inv;
    }

    const float gamma = *gammap;
    const int g8 = lane >> 2, t4 = lane & 3;
    const int m0 = (warp & 1) * 48, n0 = (warp >> 1) * 32;
    for (int c0 = 0; c0 < CC; c0 += 128) {
        __syncthreads();
        for (int idx = tid; idx < WW * 32; idx += 256) {
            int u0 = idx >> 5, c4 = (idx & 31) * 4;
            float4 v = *(const float4*)(g_v + (size_t)(nbase + u0) * CC + c0 + c4);
            uint4 u = { f2tf32(v.x), f2tf32(v.y), f2tf32(v.z), f2tf32(v.w) };
            *(uint4*)(Vsu + u0 * VS_STRIDE + c4) = u;
        }
        __syncthreads();

        float acc[3][4][4] = {};
        #pragma unroll
        for (int ks = 0; ks < 12; ++ks) {
            const int kb = ks * 8;
            uint32_t a[3][4], bf[4][2];
            #pragma unroll
            for (int mi = 0; mi < 3; ++mi) {
                const int r0 = m0 + mi * 16 + g8;
                a[mi][0] = Psu[(r0    ) * PS_STRIDE + kb + t4    ];
                a[mi][1] = Psu[(r0 + 8) * PS_STRIDE + kb + t4    ];
                a[mi][2] = Psu[(r0    ) * PS_STRIDE + kb + t4 + 4];
                a[mi][3] = Psu[(r0 + 8) * PS_STRIDE + kb + t4 + 4];
            }
            #pragma unroll
            for (int ni = 0; ni < 4; ++ni) {
                const int n = n0 + ni * 8 + g8;
                bf[ni][0] = Vsu[(kb + t4    ) * VS_STRIDE + n];
                bf[ni][1] = Vsu[(kb + t4 + 4) * VS_STRIDE + n];
            }
            #pragma unroll
            for (int mi = 0; mi < 3; ++mi)
                #pragma unroll
                for (int ni = 0; ni < 4; ++ni)
                    mma_tf32(acc[mi][ni], a[mi], bf[ni]);
        }

        #pragma unroll
        for (int mi = 0; mi < 3; ++mi) {
            const int rA = m0 + mi * 16 + g8;
            const int rB = rA + 8;
            const float fvA = fv[rA], fhA = fh[rA];
            const float fvB = fv[rB], fhB = fh[rB];
            const size_t oA = (size_t)(nbase + rA) * CC;
            const size_t oB = (size_t)(nbase + rB) * CC;
            #pragma unroll
            for (int ni = 0; ni < 4; ++ni) {
                const int col = c0 + n0 + ni * 8 + 2 * t4;
                float2 avA = *(const float2*)(g_accv + oA + col);
                float2 xvA = *(const float2*)(x + oA + col);
                float2 avB = *(const float2*)(g_accv + oB + col);
                float2 xvB = *(const float2*)(x + oB + col);
                float2 o0, o1;
                o0.x = xvA.x + gamma * (fvA * avA.x + fhA * acc[mi][ni][0]);
                o0.y = xvA.y + gamma * (fvA * avA.y + fhA * acc[mi][ni][1]);
                o1.x = xvB.x + gamma * (fvB * avB.x + fhB * acc[mi][ni][2]);
                o1.y = xvB.y + gamma * (fvB * avB.y + fhB * acc[mi][ni][3]);
                *(float2*)(out + oA + col) = o0;
                *(float2*)(out + oB + col) = o1;
            }
        }
    }
}

// ---------------- launch ----------------------------------------------------
extern "C" void kernel_launch(void* const* d_in, const int* in_sizes, int n_in,
                              void* d_out, int out_size)
{
    const float* x  = (const float*)d_in[0];
    const float* Wq = (const float*)d_in[1];
    const float* bq = (const float*)d_in[2];
    const float* Wk = (const float*)d_in[3];
    const float* bk = (const float*)d_in[4];
    const float* Wv = (const float*)d_in[5];
    const float* bv = (const float*)d_in[6];
    const float* gm = (const float*)d_in[7];
    float* out = (float*)d_out;

    cudaFuncSetAttribute(col_attn, cudaFuncAttributeMaxDynamicSharedMemorySize, SMEM_BYTES);
    cudaFuncSetAttribute(row_attn, cudaFuncAttributeMaxDynamicSharedMemorySize, SMEM_BYTES);

    dim3 gA(10, 576);
    qkv_gemm<<<gA, 256>>>(x, Wq, bq, Wk, bk, Wv, bv);
    col_attn<<<768, 256, SMEM_BYTES>>>();
    row_attn<<<768, 256, SMEM_BYTES>>>(x, gm, out);
}